// round 15
// baseline (speedup 1.0000x reference)
#include <cuda_runtime.h>

// ZBL pair energy + segment-sum into per-atom energies.
//
// Inputs (metadata order; JAX default x64-off stores "int64" as int32):
//   d_in[0] Z               float32 [4]
//   d_in[1] r               float32 [E]          (E = 6,400,000)
//   d_in[2] per_atom_energy float32 [n_atoms,1]  (n_atoms = 100,000)
//   d_in[3] atom_types      int32   [n_atoms]
//   d_in[4] edge_index      int32   [2, E]
// Output: float32 [n_atoms, 1]
//
// Regime (R5-R14): L1tex/LSU bound (REDG ~23us floor + LDS ~8us + streams).
// Hot loop is at its plateau (41.4us); this round trims startup overheads only:
// vectorized smem table staging + prologue-load/table-load overlap.

#define ZBL_QQ        7.1998225f        // 14.399645 * 0.5
#define ZBL_INV_A0    (1.0f / 0.4685f)
#define ZBL_INV_RMAX  (1.0f / 6.0f)
#define LOG2E         1.4426950408889634f
#define ZBL_D1 (-0.20162f)
#define ZBL_D2 (-0.40290f)
#define ZBL_D3 (-0.94229f)
#define ZBL_D4 (-3.19980f)

#define NTHREADS 256
#define NBLOCKS  1216

// Shared-memory LUT capacity: 6400 words * 16 types = 102400 atoms.
#define SMEM_WORDS 6400
// Fallback global packed buffer: 1M words = 16M atoms (4MB static).
#define MAX_PACK_WORDS (1 << 20)
__device__ unsigned g_packed_types[MAX_PACK_WORDS];

__device__ __forceinline__ float ex2_approx(float x) {
    float y; asm("ex2.approx.f32 %0, %1;" : "=f"(y) : "f"(x)); return y;
}
__device__ __forceinline__ float rcp_approx(float x) {
    float y; asm("rcp.approx.f32 %0, %1;" : "=f"(y) : "f"(x)); return y;
}

// Fused prep: out = per_atom_energy (float4 copy) AND pack types 2-bit/atom.
__global__ void prep_kernel(const float* __restrict__ pae,
                            float* __restrict__ out,
                            const int* __restrict__ types,
                            int n_atoms, int n_words)
{
    const int i = blockIdx.x * blockDim.x + threadIdx.x;
    const int nvec4 = n_atoms >> 2;

    if (i < nvec4)
        reinterpret_cast<float4*>(out)[i] =
            reinterpret_cast<const float4*>(pae)[i];
    if (i == 0)
        for (int a = nvec4 << 2; a < n_atoms; a++) out[a] = pae[a];

    if (i < n_words) {
        unsigned v = 0;
        const int base = i << 4;
        if (base + 16 <= n_atoms) {
            const int4* t4 = reinterpret_cast<const int4*>(types + base);
            #pragma unroll
            for (int q = 0; q < 4; q++) {
                int4 w = t4[q];
                v |= ((unsigned)w.x & 3u) << ((q * 4 + 0) * 2);
                v |= ((unsigned)w.y & 3u) << ((q * 4 + 1) * 2);
                v |= ((unsigned)w.z & 3u) << ((q * 4 + 2) * 2);
                v |= ((unsigned)w.w & 3u) << ((q * 4 + 3) * 2);
            }
        } else {
            for (int k = 0; k < 16; k++) {
                int a = base + k;
                unsigned t = (a < n_atoms) ? ((unsigned)types[a] & 3u) : 0u;
                v |= t << (k * 2);
            }
        }
        g_packed_types[i] = v;
    }
}

// Per-edge ZBL energy. 4 edges/thread/iter, depth-3 register pipeline.
template <bool USE_SMEM>
__global__ void __launch_bounds__(NTHREADS)
zbl_edge_kernel(const float* __restrict__ r,
                const int* __restrict__ e_i,
                const int* __restrict__ e_j,
                const float* __restrict__ Z,
                float* __restrict__ out,
                int E, int n_words)
{
    __shared__ unsigned s_pack[USE_SMEM ? SMEM_WORDS : 1];
    // Per-pair: x = (Zi^0.23 + Zj^0.23)/a0 * log2e,  y = QQ*Zi*Zj
    __shared__ float2 s_pair[16];
    __shared__ float s_zp[4], s_z[4];

    const int tid = threadIdx.x;

    const int nvec   = E >> 2;
    const int stride = gridDim.x * blockDim.x;
    int t0 = blockIdx.x * blockDim.x + tid;

    // ---- Startup phase: overlap table staging with pipeline prologue. ----

    // Vectorized table staging: int4 loads (6400/4/256 = ~6 iters max).
    if (USE_SMEM) {
        const int nw4 = n_words >> 2;
        const int4* src4 = reinterpret_cast<const int4*>(g_packed_types);
        int4* dst4 = reinterpret_cast<int4*>(s_pack);
        for (int w = tid; w < nw4; w += NTHREADS)
            dst4[w] = src4[w];
        for (int w = (nw4 << 2) + tid; w < n_words; w += NTHREADS)
            s_pack[w] = g_packed_types[w];
    }

    // Pipeline prologue (independent of smem): issue these LDGs now so their
    // DRAM latency overlaps the table staging above.
    const bool hasA = t0 < nvec;
    float4 rA; int4 iA, jA;
    if (hasA) {
        rA = __ldcs(reinterpret_cast<const float4*>(r) + t0);
        iA = __ldcs(reinterpret_cast<const int4*>(e_i) + t0);
        jA = __ldcs(reinterpret_cast<const int4*>(e_j) + t0);
    }
    int  t1   = t0 + stride;
    bool hasB = hasA && (t1 < nvec);
    float4 rB; int4 iB, jB;
    if (hasB) {
        rB = __ldcs(reinterpret_cast<const float4*>(r) + t1);
        iB = __ldcs(reinterpret_cast<const int4*>(e_i) + t1);
        jB = __ldcs(reinterpret_cast<const int4*>(e_j) + t1);
    }

    // Small coefficient tables.
    if (tid < 4) {
        float z = Z[tid];
        s_z[tid]  = z;
        s_zp[tid] = __powf(z, 0.23f);
    }
    __syncthreads();
    if (tid < 16) {
        int ti = tid >> 2, tj = tid & 3;
        s_pair[tid] = make_float2(
            (s_zp[ti] + s_zp[tj]) * ZBL_INV_A0 * LOG2E,
            ZBL_QQ * s_z[ti] * s_z[tj]);
    }
    __syncthreads();

    const unsigned* __restrict__ tbl = USE_SMEM ? s_pack : g_packed_types;

    // ---- Main depth-3 pipelined loop (identical hot path to R14). ----
    if (hasA) {
        for (;;) {
            // Stage C: load 2 iterations ahead.
            const int  t2   = t1 + stride;
            const bool hasC = hasB && (t2 < nvec);
            float4 rC; int4 iC, jC;
            if (hasC) {
                rC = __ldcs(reinterpret_cast<const float4*>(r) + t2);
                iC = __ldcs(reinterpret_cast<const int4*>(e_i) + t2);
                jC = __ldcs(reinterpret_cast<const int4*>(e_j) + t2);
            }

            // Compute stage A.
            {
                const int   ii[4] = {iA.x, iA.y, iA.z, iA.w};
                const int   jj[4] = {jA.x, jA.y, jA.z, jA.w};
                const float rv[4] = {rA.x, rA.y, rA.z, rA.w};

                // Phase 1: batch all smem lookups (latency overlap).
                bool   live[4];
                float2 pr[4];
                #pragma unroll
                for (int k = 0; k < 4; k++) {
                    live[k] = rv[k] < 6.0f;
                    const int ia = live[k] ? ii[k] : 0;  // dead: broadcast word 0
                    const int ja = live[k] ? jj[k] : 0;
                    const unsigned wi = tbl[ia >> 4];
                    const unsigned wj = tbl[ja >> 4];
                    const int ti = (wi >> ((ia & 15) << 1)) & 3;
                    const int tj = (wj >> ((ja & 15) << 1)) & 3;
                    pr[k] = s_pair[(ti << 2) | tj];
                }

                // Phase 2: math + predicated atomic per edge.
                #pragma unroll
                for (int k = 0; k < 4; k++) {
                    const float rk = rv[k];
                    const float brk = pr[k].x * rk;
                    const float e1 = ex2_approx(ZBL_D1 * brk);
                    const float e2 = ex2_approx(ZBL_D2 * brk);
                    const float e3 = ex2_approx(ZBL_D3 * brk);
                    const float e4 = ex2_approx(ZBL_D4 * brk);
                    float psi = fmaf(0.02817f, e1,
                                fmaf(0.28022f, e2,
                                fmaf(0.50986f, e3, 0.18175f * e4)));

                    // Cutoff, p=6: 1 - 28 rr^6 + 48 rr^7 - 21 rr^8
                    const float rr  = rk * ZBL_INV_RMAX;
                    const float rr2 = rr * rr;
                    const float rr3 = rr2 * rr;
                    const float rr6 = rr3 * rr3;
                    const float cut = fmaf(rr6,
                        fmaf(rr, fmaf(rr, -21.0f, 48.0f), -28.0f), 1.0f);

                    const float eng = pr[k].y * psi * rcp_approx(rk) * cut;
                    if (live[k]) atomicAdd(&out[ii[k]], eng);
                }
            }

            if (!hasB) break;
            // Rotate pipeline stages.
            rA = rB; iA = iB; jA = jB;
            rB = rC; iB = iC; jB = jC;
            t1 = t2; hasB = hasC;
        }
    }

    // Scalar tail (E not divisible by 4): at most 3 edges, one thread.
    if (blockIdx.x == 0 && tid == 0) {
        for (int e = nvec << 2; e < E; e++) {
            float rk = r[e];
            if (rk >= 6.0f) continue;
            int i = e_i[e], j = e_j[e];
            unsigned wi = tbl[i >> 4];
            unsigned wj = tbl[j >> 4];
            int ti = (wi >> ((i & 15) << 1)) & 3;
            int tj = (wj >> ((j & 15) << 1)) & 3;
            float2 pr = s_pair[(ti << 2) | tj];
            float brk = pr.x * rk;
            float e1 = ex2_approx(ZBL_D1 * brk);
            float e2 = ex2_approx(ZBL_D2 * brk);
            float e3 = ex2_approx(ZBL_D3 * brk);
            float e4 = ex2_approx(ZBL_D4 * brk);
            float psi = fmaf(0.02817f, e1,
                        fmaf(0.28022f, e2,
                        fmaf(0.50986f, e3, 0.18175f * e4)));
            float rr  = rk * ZBL_INV_RMAX;
            float rr2 = rr * rr;
            float rr6 = rr2 * rr2 * rr2;
            float cut = fmaf(rr6, fmaf(rr, fmaf(rr, -21.0f, 48.0f), -28.0f), 1.0f);
            float eng = pr.y * psi * rcp_approx(rk);
            atomicAdd(&out[i], eng * cut);
        }
    }
}

extern "C" void kernel_launch(void* const* d_in, const int* in_sizes, int n_in,
                              void* d_out, int out_size)
{
    const float* Z     = (const float*)d_in[0];
    const float* r     = (const float*)d_in[1];
    const float* pae   = (const float*)d_in[2];
    const int*   types = (const int*)d_in[3];
    const int*   eidx  = (const int*)d_in[4];
    float*       out   = (float*)d_out;

    const int E       = in_sizes[1];
    const int n_atoms = in_sizes[2];
    const int n_words = (n_atoms + 15) >> 4;

    {
        int work = (n_atoms >> 2) > n_words ? (n_atoms >> 2) : n_words;
        if (work < 1) work = 1;
        prep_kernel<<<(work + 511) / 512, 512>>>(pae, out, types, n_atoms, n_words);
    }

    if (n_words <= SMEM_WORDS) {
        zbl_edge_kernel<true><<<NBLOCKS, NTHREADS>>>(r, eidx, eidx + E, Z, out, E, n_words);
    } else {
        zbl_edge_kernel<false><<<NBLOCKS, NTHREADS>>>(r, eidx, eidx + E, Z, out, E, n_words);
    }
}

// round 16
// speedup vs baseline: 1.0008x; 1.0008x over previous
#include <cuda_runtime.h>

// ZBL pair energy + segment-sum into per-atom energies.
//
// Inputs (metadata order; JAX default x64-off stores "int64" as int32):
//   d_in[0] Z               float32 [4]
//   d_in[1] r               float32 [E]          (E = 6,400,000)
//   d_in[2] per_atom_energy float32 [n_atoms,1]  (n_atoms = 100,000)
//   d_in[3] atom_types      int32   [n_atoms]
//   d_in[4] edge_index      int32   [2, E]
// Output: float32 [n_atoms, 1]
//
// Regime (R5-R15): L1tex/LSU bound (REDG ~24us + LDS ~8us + LDG ~2us floor).
// R16: drop dead-lane clamp (indices always valid; kills bank-0 hotspot and
// 4 SELs/tile) + NBLOCKS=1250 (exactly 5 tiles/thread, no straggler tail).

#define ZBL_QQ        7.1998225f        // 14.399645 * 0.5
#define ZBL_INV_A0    (1.0f / 0.4685f)
#define ZBL_INV_RMAX  (1.0f / 6.0f)
#define LOG2E         1.4426950408889634f
#define ZBL_D1 (-0.20162f)
#define ZBL_D2 (-0.40290f)
#define ZBL_D3 (-0.94229f)
#define ZBL_D4 (-3.19980f)

#define NTHREADS 256
#define NBLOCKS  1250     // 320,000 threads: 1.6M tiles / 320K = exactly 5 each

// Shared-memory LUT capacity: 6400 words * 16 types = 102400 atoms.
#define SMEM_WORDS 6400
// Fallback global packed buffer: 1M words = 16M atoms (4MB static).
#define MAX_PACK_WORDS (1 << 20)
__device__ unsigned g_packed_types[MAX_PACK_WORDS];

__device__ __forceinline__ float ex2_approx(float x) {
    float y; asm("ex2.approx.f32 %0, %1;" : "=f"(y) : "f"(x)); return y;
}
__device__ __forceinline__ float rcp_approx(float x) {
    float y; asm("rcp.approx.f32 %0, %1;" : "=f"(y) : "f"(x)); return y;
}

// Fused prep: out = per_atom_energy (float4 copy) AND pack types 2-bit/atom.
__global__ void prep_kernel(const float* __restrict__ pae,
                            float* __restrict__ out,
                            const int* __restrict__ types,
                            int n_atoms, int n_words)
{
    const int i = blockIdx.x * blockDim.x + threadIdx.x;
    const int nvec4 = n_atoms >> 2;

    if (i < nvec4)
        reinterpret_cast<float4*>(out)[i] =
            reinterpret_cast<const float4*>(pae)[i];
    if (i == 0)
        for (int a = nvec4 << 2; a < n_atoms; a++) out[a] = pae[a];

    if (i < n_words) {
        unsigned v = 0;
        const int base = i << 4;
        if (base + 16 <= n_atoms) {
            const int4* t4 = reinterpret_cast<const int4*>(types + base);
            #pragma unroll
            for (int q = 0; q < 4; q++) {
                int4 w = t4[q];
                v |= ((unsigned)w.x & 3u) << ((q * 4 + 0) * 2);
                v |= ((unsigned)w.y & 3u) << ((q * 4 + 1) * 2);
                v |= ((unsigned)w.z & 3u) << ((q * 4 + 2) * 2);
                v |= ((unsigned)w.w & 3u) << ((q * 4 + 3) * 2);
            }
        } else {
            for (int k = 0; k < 16; k++) {
                int a = base + k;
                unsigned t = (a < n_atoms) ? ((unsigned)types[a] & 3u) : 0u;
                v |= t << (k * 2);
            }
        }
        g_packed_types[i] = v;
    }
}

// Per-edge ZBL energy. 4 edges/thread/iter, depth-3 register pipeline.
template <bool USE_SMEM>
__global__ void __launch_bounds__(NTHREADS)
zbl_edge_kernel(const float* __restrict__ r,
                const int* __restrict__ e_i,
                const int* __restrict__ e_j,
                const float* __restrict__ Z,
                float* __restrict__ out,
                int E, int n_words)
{
    __shared__ unsigned s_pack[USE_SMEM ? SMEM_WORDS : 1];
    // Per-pair: x = (Zi^0.23 + Zj^0.23)/a0 * log2e,  y = QQ*Zi*Zj
    __shared__ float2 s_pair[16];
    __shared__ float s_zp[4], s_z[4];

    const int tid = threadIdx.x;
    if (tid < 4) {
        float z = Z[tid];
        s_z[tid]  = z;
        s_zp[tid] = __powf(z, 0.23f);
    }
    __syncthreads();
    if (tid < 16) {
        int ti = tid >> 2, tj = tid & 3;
        s_pair[tid] = make_float2(
            (s_zp[ti] + s_zp[tj]) * ZBL_INV_A0 * LOG2E,
            ZBL_QQ * s_z[ti] * s_z[tj]);
    }
    if (USE_SMEM) {
        const int nw4 = n_words >> 2;
        const int4* src4 = reinterpret_cast<const int4*>(g_packed_types);
        int4* dst4 = reinterpret_cast<int4*>(s_pack);
        for (int w = tid; w < nw4; w += NTHREADS)
            dst4[w] = src4[w];
        for (int w = (nw4 << 2) + tid; w < n_words; w += NTHREADS)
            s_pack[w] = g_packed_types[w];
    }
    __syncthreads();

    const unsigned* __restrict__ tbl = USE_SMEM ? s_pack : g_packed_types;

    const int nvec   = E >> 2;
    const int stride = gridDim.x * blockDim.x;
    int t0 = blockIdx.x * blockDim.x + tid;

    if (t0 < nvec) {
        // Prologue: stage A (compute-next) and stage B (1 ahead).
        float4 rA = __ldcs(reinterpret_cast<const float4*>(r) + t0);
        int4   iA = __ldcs(reinterpret_cast<const int4*>(e_i) + t0);
        int4   jA = __ldcs(reinterpret_cast<const int4*>(e_j) + t0);

        int  t1   = t0 + stride;
        bool hasB = t1 < nvec;
        float4 rB; int4 iB, jB;
        if (hasB) {
            rB = __ldcs(reinterpret_cast<const float4*>(r) + t1);
            iB = __ldcs(reinterpret_cast<const int4*>(e_i) + t1);
            jB = __ldcs(reinterpret_cast<const int4*>(e_j) + t1);
        }

        for (;;) {
            // Stage C: load 2 iterations ahead.
            const int  t2   = t1 + stride;
            const bool hasC = hasB && (t2 < nvec);
            float4 rC; int4 iC, jC;
            if (hasC) {
                rC = __ldcs(reinterpret_cast<const float4*>(r) + t2);
                iC = __ldcs(reinterpret_cast<const int4*>(e_i) + t2);
                jC = __ldcs(reinterpret_cast<const int4*>(e_j) + t2);
            }

            // Compute stage A.
            {
                const int   ii[4] = {iA.x, iA.y, iA.z, iA.w};
                const int   jj[4] = {jA.x, jA.y, jA.z, jA.w};
                const float rv[4] = {rA.x, rA.y, rA.z, rA.w};

                // Phase 1: batch all smem lookups (latency overlap).
                // Indices are ALWAYS valid atom ids — no dead-lane clamp
                // (avoids SELs and the bank-0 hotspot).
                float2 pr[4];
                #pragma unroll
                for (int k = 0; k < 4; k++) {
                    const unsigned wi = tbl[ii[k] >> 4];
                    const unsigned wj = tbl[jj[k] >> 4];
                    const int ti = (wi >> ((ii[k] & 15) << 1)) & 3;
                    const int tj = (wj >> ((jj[k] & 15) << 1)) & 3;
                    pr[k] = s_pair[(ti << 2) | tj];
                }

                // Phase 2: math + predicated atomic per edge.
                #pragma unroll
                for (int k = 0; k < 4; k++) {
                    const float rk = rv[k];
                    const float brk = pr[k].x * rk;
                    const float e1 = ex2_approx(ZBL_D1 * brk);
                    const float e2 = ex2_approx(ZBL_D2 * brk);
                    const float e3 = ex2_approx(ZBL_D3 * brk);
                    const float e4 = ex2_approx(ZBL_D4 * brk);
                    float psi = fmaf(0.02817f, e1,
                                fmaf(0.28022f, e2,
                                fmaf(0.50986f, e3, 0.18175f * e4)));

                    // Cutoff, p=6: 1 - 28 rr^6 + 48 rr^7 - 21 rr^8
                    const float rr  = rk * ZBL_INV_RMAX;
                    const float rr2 = rr * rr;
                    const float rr3 = rr2 * rr;
                    const float rr6 = rr3 * rr3;
                    const float cut = fmaf(rr6,
                        fmaf(rr, fmaf(rr, -21.0f, 48.0f), -28.0f), 1.0f);

                    const float eng = pr[k].y * psi * rcp_approx(rk) * cut;
                    if (rk < 6.0f) atomicAdd(&out[ii[k]], eng);
                }
            }

            if (!hasB) break;
            // Rotate pipeline stages.
            rA = rB; iA = iB; jA = jB;
            rB = rC; iB = iC; jB = jC;
            t1 = t2; hasB = hasC;
        }
    }

    // Scalar tail (E not divisible by 4): at most 3 edges, one thread.
    if (blockIdx.x == 0 && tid == 0) {
        for (int e = nvec << 2; e < E; e++) {
            float rk = r[e];
            if (rk >= 6.0f) continue;
            int i = e_i[e], j = e_j[e];
            unsigned wi = tbl[i >> 4];
            unsigned wj = tbl[j >> 4];
            int ti = (wi >> ((i & 15) << 1)) & 3;
            int tj = (wj >> ((j & 15) << 1)) & 3;
            float2 pr = s_pair[(ti << 2) | tj];
            float brk = pr.x * rk;
            float e1 = ex2_approx(ZBL_D1 * brk);
            float e2 = ex2_approx(ZBL_D2 * brk);
            float e3 = ex2_approx(ZBL_D3 * brk);
            float e4 = ex2_approx(ZBL_D4 * brk);
            float psi = fmaf(0.02817f, e1,
                        fmaf(0.28022f, e2,
                        fmaf(0.50986f, e3, 0.18175f * e4)));
            float rr  = rk * ZBL_INV_RMAX;
            float rr2 = rr * rr;
            float rr6 = rr2 * rr2 * rr2;
            float cut = fmaf(rr6, fmaf(rr, fmaf(rr, -21.0f, 48.0f), -28.0f), 1.0f);
            float eng = pr.y * psi * rcp_approx(rk);
            atomicAdd(&out[i], eng * cut);
        }
    }
}

extern "C" void kernel_launch(void* const* d_in, const int* in_sizes, int n_in,
                              void* d_out, int out_size)
{
    const float* Z     = (const float*)d_in[0];
    const float* r     = (const float*)d_in[1];
    const float* pae   = (const float*)d_in[2];
    const int*   types = (const int*)d_in[3];
    const int*   eidx  = (const int*)d_in[4];
    float*       out   = (float*)d_out;

    const int E       = in_sizes[1];
    const int n_atoms = in_sizes[2];
    const int n_words = (n_atoms + 15) >> 4;

    {
        int work = (n_atoms >> 2) > n_words ? (n_atoms >> 2) : n_words;
        if (work < 1) work = 1;
        prep_kernel<<<(work + 511) / 512, 512>>>(pae, out, types, n_atoms, n_words);
    }

    if (n_words <= SMEM_WORDS) {
        zbl_edge_kernel<true><<<NBLOCKS, NTHREADS>>>(r, eidx, eidx + E, Z, out, E, n_words);
    } else {
        zbl_edge_kernel<false><<<NBLOCKS, NTHREADS>>>(r, eidx, eidx + E, Z, out, E, n_words);
    }
}